// round 13
// baseline (speedup 1.0000x reference)
#include <cuda_runtime.h>
#include <cuda_fp16.h>
#include <cstdint>
#include <math.h>

#define TB 8192      // tokens = B*S
#define HD 1024
#define NE 8
#define FF 4096

// GEMM tiling: CTA 128x128, 4 warps (2x2), warptile 64x64, fp16 MMA k16, ldmatrix
#define GT 128       // GEMM threads per CTA
#define BM 128
#define BN 128
#define KC 64        // k-elements (halves) per chunk = 128B per row
#define STAGES 3
#define ROWB 144     // SMEM row stride bytes (128 data + 16 pad); LDSM conflict-free
#define ROW_U32 36
#define TSTG (128 * ROWB)                 // 18432 B per tile stage
#define B_OFF (STAGES * TSTG)             // 55296
#define LIST_OFF (2 * STAGES * TSTG)      // 110592
#define SMEM_SZ (LIST_OFF + 2048)         // 112640 -> 2 CTA/SM

// ---- scratch (static device arrays; no allocation) ----
__device__ __half g_xh [(size_t)TB * HD];        // fp16 x (written by router)
__device__ __half g_h  [(size_t)2 * TB * FF];    // fp16 gelu(x@W1) per slot
__device__ __half g_w1h[(size_t)NE * FF * HD];   // W1 transposed [f][h] fp16
__device__ __half g_w2h[(size_t)NE * HD * FF];   // W2 transposed [h][f] fp16
__device__ int   g_cnt[NE];
__device__ int   g_tok[NE * TB];
__device__ int   g_slot[NE * TB];
__device__ float g_p0[TB];

// ---- helpers ----
__device__ __forceinline__ uint32_t smem_u32(const void* p) {
    uint32_t a;
    asm("{ .reg .u64 t; cvta.to.shared.u64 t, %1; cvt.u32.u64 %0, t; }" : "=r"(a) : "l"(p));
    return a;
}
__device__ __forceinline__ void cp16(uint32_t s, const void* g) {
    asm volatile("cp.async.cg.shared.global [%0], [%1], 16;" :: "r"(s), "l"(g));
}
#define CP_COMMIT() asm volatile("cp.async.commit_group;" ::: "memory")
#define CP_WAIT2()  asm volatile("cp.async.wait_group 2;" ::: "memory")

#define MMA_F16(d, a, b) \
    asm volatile("mma.sync.aligned.m16n8k16.row.col.f32.f16.f16.f32 " \
        "{%0,%1,%2,%3}, {%4,%5,%6,%7}, {%8,%9}, {%0,%1,%2,%3};" \
        : "+f"((d)[0]), "+f"((d)[1]), "+f"((d)[2]), "+f"((d)[3]) \
        : "r"((a)[0]), "r"((a)[1]), "r"((a)[2]), "r"((a)[3]), \
          "r"((b)[0]), "r"((b)[1]))

#define LDSM4(r, a) \
    asm volatile("ldmatrix.sync.aligned.m8n8.x4.shared.b16 {%0,%1,%2,%3}, [%4];" \
        : "=r"((r)[0]), "=r"((r)[1]), "=r"((r)[2]), "=r"((r)[3]) : "r"(a))

__device__ __forceinline__ float fgelu(float v) {
    float z = 0.7978845608028654f * (v + 0.044715f * v * v * v);
    float e = __expf(2.0f * z);
    float t = 1.0f - 2.0f / (e + 1.0f);   // tanh(z)
    return 0.5f * v * (1.0f + t);
}

// ---------------------------------------------------------------------------
// Zero output + expert counters
// ---------------------------------------------------------------------------
__global__ void k_zero(float* __restrict__ out, int n4) {
    int i = blockIdx.x * blockDim.x + threadIdx.x;
    float4 z = make_float4(0.f, 0.f, 0.f, 0.f);
    for (int j = i; j < n4; j += gridDim.x * blockDim.x)
        ((float4*)out)[j] = z;
    if (i < NE) g_cnt[i] = 0;
}

// ---------------------------------------------------------------------------
// Transpose + convert one expert-stack of weights: [E][K][N] fp32 -> [E][N][K] fp16
// ---------------------------------------------------------------------------
__global__ void k_cvt_t(const float* __restrict__ src, __half* __restrict__ dst,
                        int K, int N) {
    __shared__ float tile[32][33];
    const int e  = blockIdx.z;
    const int nb = blockIdx.x * 32;
    const int kb = blockIdx.y * 32;
    const float* s = src + (size_t)e * K * N;
    __half* d = dst + (size_t)e * K * N;
    const int tid = threadIdx.x;   // 256
#pragma unroll
    for (int p = 0; p < 4; p++) {
        int idx = tid + p * 256;
        int r = idx >> 5, c = idx & 31;
        tile[r][c] = s[(size_t)(kb + r) * N + nb + c];
    }
    __syncthreads();
#pragma unroll
    for (int p = 0; p < 4; p++) {
        int idx = tid + p * 256;
        int r = idx >> 5, c = idx & 31;
        d[(size_t)(nb + r) * K + kb + c] = __float2half_rn(tile[c][r]);
    }
}

// ---------------------------------------------------------------------------
// Router (also writes fp16 x into g_xh)
// ---------------------------------------------------------------------------
__global__ void k_router(const float* __restrict__ x,
                         const float* __restrict__ Wr,
                         const float* __restrict__ br) {
    int warp = (blockIdx.x * blockDim.x + threadIdx.x) >> 5;
    int lane = threadIdx.x & 31;
    if (warp >= TB) return;
    const float* xr = x + (size_t)warp * HD;
    __half* gxr = g_xh + (size_t)warp * HD;

    float acc[NE];
#pragma unroll
    for (int e = 0; e < NE; e++) acc[e] = 0.f;
    for (int h = lane; h < HD; h += 32) {
        float xv = xr[h];
        gxr[h] = __float2half_rn(xv);
        float4 w0 = *(const float4*)(Wr + h * NE);
        float4 w1 = *(const float4*)(Wr + h * NE + 4);
        acc[0] += xv * w0.x; acc[1] += xv * w0.y;
        acc[2] += xv * w0.z; acc[3] += xv * w0.w;
        acc[4] += xv * w1.x; acc[5] += xv * w1.y;
        acc[6] += xv * w1.z; acc[7] += xv * w1.w;
    }
#pragma unroll
    for (int e = 0; e < NE; e++)
#pragma unroll
        for (int off = 16; off > 0; off >>= 1)
            acc[e] += __shfl_xor_sync(0xffffffffu, acc[e], off);
    if (lane == 0) {
#pragma unroll
        for (int e = 0; e < NE; e++) acc[e] += br[e];
        int i1 = 0; float l1 = acc[0];
#pragma unroll
        for (int e = 1; e < NE; e++) if (acc[e] > l1) { l1 = acc[e]; i1 = e; }
        int i2 = -1; float l2 = -3.0e38f;
#pragma unroll
        for (int e = 0; e < NE; e++) if (e != i1 && acc[e] > l2) { l2 = acc[e]; i2 = e; }
        g_p0[warp] = 1.0f / (1.0f + expf(l2 - l1));
        int p = atomicAdd(&g_cnt[i1], 1);
        g_tok[i1 * TB + p]  = warp;
        g_slot[i1 * TB + p] = 2 * warp;
        p = atomicAdd(&g_cnt[i2], 1);
        g_tok[i2 * TB + p]  = warp;
        g_slot[i2 * TB + p] = 2 * warp + 1;
    }
}

// ---------------------------------------------------------------------------
// Grouped GEMM on mma.sync fp16 (fp32 accumulate), ldmatrix fragment loads.
// A: [row][k] fp16 k-contiguous (g_xh or g_h). B: transposed weights [n][k] fp16.
// MODE 0: g_h[slot] = fp16(gelu(x[tok] @ W1[e] + b1[e]))        (K=HD, N over FF)
// MODE 1: out[tok] += p0 * ((g_h[slot] @ W2[e]) + b2[e]) atomic (K=FF, N over HD)
// ---------------------------------------------------------------------------
template <int MODE>
__global__ __launch_bounds__(GT, 2)
void k_gemm(const __half* __restrict__ W, const float* __restrict__ bias,
            float* __restrict__ outp) {
    constexpr int KTOT = MODE ? FF : HD;
    constexpr int LDA  = MODE ? FF : HD;
    constexpr int OROW = MODE ? HD : FF;
    constexpr int NC   = KTOT / KC;

    const int e  = blockIdx.z;
    const int me = g_cnt[e];
    const int mt = blockIdx.y;
    if (mt * BM >= me) return;
    const int ntb = blockIdx.x * BN;

    extern __shared__ char smraw[];
    char* As = smraw;
    char* Bs = smraw + B_OFF;
    int*   stok  = (int*)(smraw + LIST_OFF);
    int*   sslot = stok + 128;
    float* sp0   = (float*)(sslot + 128);

    const int tid  = threadIdx.x;
    const int wid  = tid >> 5;
    const int lane = tid & 31;
    const int wm   = wid >> 1;       // 0..1
    const int wn   = wid & 1;        // 0..1
    const int lr   = lane >> 2;      // 0..7  (groupID)
    const int lc   = lane & 3;       // 0..3  (threadID_in_group)

    {
        int i = mt * BM + tid;
        int tok = 0, slot = -1;
        if (i < me) { tok = g_tok[e * TB + i]; slot = g_slot[e * TB + i]; }
        stok[tid] = tok; sslot[tid] = slot;
        if (MODE == 1) sp0[tid] = g_p0[tok];
    }
    __syncthreads();

    // ---- cp.async mappings ----
    const int mrow = tid >> 3;            // 0..15
    const int mseg = tid & 7;             // 0..7
    const __half* Asrc = MODE ? (const __half*)g_h : (const __half*)g_xh;
    const __half* aptr[8];
#pragma unroll
    for (int m = 0; m < 8; m++) {
        int row = mrow + 16 * m;
        int rid = MODE ? sslot[row] : stok[row];
        if (rid < 0) rid = 0;
        aptr[m] = Asrc + (size_t)rid * LDA + mseg * 8;
    }
    const uint32_t asmA = smem_u32(As) + (uint32_t)(mrow * ROWB + mseg * 16);

    const __half* bglob = W + (size_t)e * HD * FF + (size_t)(ntb + mrow) * KTOT + mseg * 8;
    const uint32_t bsmB = smem_u32(Bs) + (uint32_t)(mrow * ROWB + mseg * 16);

#define LOAD_CHUNK(STG, C)                                                    \
    {                                                                         \
        uint32_t as_ = asmA + (STG) * TSTG;                                   \
        _Pragma("unroll")                                                     \
        for (int m = 0; m < 8; m++)                                           \
            cp16(as_ + m * (16 * ROWB), aptr[m] + (C) * KC);                  \
        const __half* bg = bglob + (size_t)(C) * KC;                          \
        uint32_t bs_ = bsmB + (STG) * TSTG;                                   \
        _Pragma("unroll")                                                     \
        for (int m = 0; m < 8; m++)                                           \
            cp16(bs_ + m * (16 * ROWB), bg + (size_t)m * 16 * KTOT);          \
    }

    float acc[4][8][4];
#pragma unroll
    for (int i = 0; i < 4; i++)
#pragma unroll
        for (int j = 0; j < 8; j++)
#pragma unroll
            for (int r = 0; r < 4; r++) acc[i][j][r] = 0.f;

    LOAD_CHUNK(0, 0); CP_COMMIT();
    LOAD_CHUNK(1, 1); CP_COMMIT();

    // ---- ldmatrix per-thread base addresses ----
    // A m16k16 tile: lanes 0-7 -> rows 0-7 klo (a0); 8-15 -> rows 8-15 klo (a1);
    //                16-23 -> rows 0-7 khi (a2); 24-31 -> rows 8-15 khi (a3).
    const uint32_t aldm = smem_u32(As) +
        (uint32_t)((wm * 64 + (lane & 15)) * ROWB + ((lane >> 4) & 1) * 16);
    // B pair of n8 tiles: lanes 0-7 -> n 0-7 klo (b[j][0]); 8-15 -> n 0-7 khi (b[j][1]);
    //                     16-23 -> n 8-15 klo; 24-31 -> n 8-15 khi.
    const uint32_t bldm = smem_u32(Bs) +
        (uint32_t)((wn * 64 + (lane & 7) + ((lane & 16) >> 1)) * ROWB + (lane & 8) * 2);

    for (int c = 0; c < NC; c++) {
        const int pf = c + STAGES - 1;
        if (pf < NC) { LOAD_CHUNK(pf % STAGES, pf); }
        CP_COMMIT();
        CP_WAIT2();
        __syncthreads();

        const int st = c % STAGES;
        const uint32_t aS = aldm + st * TSTG;
        const uint32_t bS = bldm + st * TSTG;
#pragma unroll
        for (int k16 = 0; k16 < KC / 16; k16++) {
            const uint32_t ko = k16 * 32;    // 16 halves = 32 bytes
            uint32_t af[4][4], bf4[4][4];
#pragma unroll
            for (int i = 0; i < 4; i++)
                LDSM4(af[i], aS + i * (16 * ROWB) + ko);
#pragma unroll
            for (int jj = 0; jj < 4; jj++)
                LDSM4(bf4[jj], bS + jj * (16 * ROWB) + ko);
#pragma unroll
            for (int i = 0; i < 4; i++)
#pragma unroll
                for (int j = 0; j < 8; j++)
                    MMA_F16(acc[i][j], af[i], &bf4[j >> 1][(j & 1) * 2]);
        }
        __syncthreads();
    }

    // ---- epilogue ----
    float bv[16];
#pragma unroll
    for (int j = 0; j < 8; j++) {
        float2 t = *(const float2*)(bias + e * OROW + ntb + wn * 64 + 8 * j + lc * 2);
        bv[2 * j] = t.x; bv[2 * j + 1] = t.y;
    }

#pragma unroll
    for (int i = 0; i < 4; i++) {
        const int mr0 = wm * 64 + 16 * i + lr;
        const int s0 = sslot[mr0];
        const int s1 = sslot[mr0 + 8];
#pragma unroll
        for (int j = 0; j < 8; j++) {
            const int n = ntb + wn * 64 + 8 * j + lc * 2;
            if (MODE == 0) {
                if (s0 >= 0) {
                    *(__half2*)(g_h + (size_t)s0 * OROW + n) = __floats2half2_rn(
                        fgelu(acc[i][j][0] + bv[2 * j]),
                        fgelu(acc[i][j][1] + bv[2 * j + 1]));
                }
                if (s1 >= 0) {
                    *(__half2*)(g_h + (size_t)s1 * OROW + n) = __floats2half2_rn(
                        fgelu(acc[i][j][2] + bv[2 * j]),
                        fgelu(acc[i][j][3] + bv[2 * j + 1]));
                }
            } else {
                if (s0 >= 0) {
                    float p = sp0[mr0];
                    float* op = outp + (size_t)stok[mr0] * HD + n;
                    atomicAdd(op,     p * (acc[i][j][0] + bv[2 * j]));
                    atomicAdd(op + 1, p * (acc[i][j][1] + bv[2 * j + 1]));
                }
                if (s1 >= 0) {
                    float p = sp0[mr0 + 8];
                    float* op = outp + (size_t)stok[mr0 + 8] * HD + n;
                    atomicAdd(op,     p * (acc[i][j][2] + bv[2 * j]));
                    atomicAdd(op + 1, p * (acc[i][j][3] + bv[2 * j + 1]));
                }
            }
        }
    }
}

// ---------------------------------------------------------------------------
extern "C" void kernel_launch(void* const* d_in, const int* in_sizes, int n_in,
                              void* d_out, int out_size) {
    const float* x  = (const float*)d_in[0];
    const float* Wr = (const float*)d_in[1];
    const float* br = (const float*)d_in[2];
    const float* W1 = (const float*)d_in[3];
    const float* b1 = (const float*)d_in[4];
    const float* W2 = (const float*)d_in[5];
    const float* b2 = (const float*)d_in[6];
    float* out = (float*)d_out;

    cudaFuncSetAttribute(k_gemm<0>, cudaFuncAttributeMaxDynamicSharedMemorySize, SMEM_SZ);
    cudaFuncSetAttribute(k_gemm<1>, cudaFuncAttributeMaxDynamicSharedMemorySize, SMEM_SZ);

    __half* gw1; cudaGetSymbolAddress((void**)&gw1, g_w1h);
    __half* gw2; cudaGetSymbolAddress((void**)&gw2, g_w2h);

    k_zero<<<2048, 256>>>(out, out_size / 4);
    k_router<<<TB / 8, 256>>>(x, Wr, br);
    // W1 [K=HD][N=FF] -> [FF][HD];  W2 [K=FF][N=HD] -> [HD][FF]
    dim3 t1(FF / 32, HD / 32, NE);
    k_cvt_t<<<t1, 256>>>(W1, gw1, HD, FF);
    dim3 t2(HD / 32, FF / 32, NE);
    k_cvt_t<<<t2, 256>>>(W2, gw2, FF, HD);
    dim3 g1(FF / BN, TB / BM, NE);   // (32, 64, 8)
    k_gemm<0><<<g1, GT, SMEM_SZ>>>(gw1, b1, nullptr);
    dim3 g2(HD / BN, TB / BM, NE);   // (8, 64, 8)
    k_gemm<1><<<g2, GT, SMEM_SZ>>>(gw2, b2, out);
}

// round 14
// speedup vs baseline: 1.0449x; 1.0449x over previous
#include <cuda_runtime.h>
#include <cuda_fp16.h>
#include <cstdint>
#include <math.h>

#define TB 8192      // tokens = B*S
#define HD 1024
#define NE 8
#define FF 4096

// GEMM tiling: CTA 128x128, 8 warps (2x4), warptile 64x32, fp16 MMA k16, ldmatrix
#define GT 256       // GEMM threads per CTA
#define BM 128
#define BN 128
#define KC 64        // k-elements (halves) per chunk = 128B per row
#define STAGES 3
#define ROWB 144     // SMEM row stride bytes (128 data + 16 pad); LDSM conflict-free
#define TSTG (128 * ROWB)                 // 18432 B per tile stage
#define B_OFF (STAGES * TSTG)             // 55296
#define LIST_OFF (2 * STAGES * TSTG)      // 110592
#define SMEM_SZ (LIST_OFF + 2048)         // 112640 -> 2 CTA/SM

// ---- scratch (static device arrays; no allocation) ----
__device__ __half g_xh [(size_t)TB * HD];        // fp16 x (written by router)
__device__ __half g_h  [(size_t)2 * TB * FF];    // fp16 gelu(x@W1) per slot
__device__ __half g_w1h[(size_t)NE * FF * HD];   // W1 transposed [f][h] fp16
__device__ __half g_w2h[(size_t)NE * HD * FF];   // W2 transposed [h][f] fp16
__device__ int   g_cnt[NE];
__device__ int   g_tok[NE * TB];
__device__ int   g_slot[NE * TB];
__device__ float g_p0[TB];

// ---- helpers ----
__device__ __forceinline__ uint32_t smem_u32(const void* p) {
    uint32_t a;
    asm("{ .reg .u64 t; cvta.to.shared.u64 t, %1; cvt.u32.u64 %0, t; }" : "=r"(a) : "l"(p));
    return a;
}
__device__ __forceinline__ void cp16(uint32_t s, const void* g) {
    asm volatile("cp.async.cg.shared.global [%0], [%1], 16;" :: "r"(s), "l"(g));
}
#define CP_COMMIT() asm volatile("cp.async.commit_group;" ::: "memory")
#define CP_WAIT2()  asm volatile("cp.async.wait_group 2;" ::: "memory")

#define MMA_F16(d, a, b) \
    asm volatile("mma.sync.aligned.m16n8k16.row.col.f32.f16.f16.f32 " \
        "{%0,%1,%2,%3}, {%4,%5,%6,%7}, {%8,%9}, {%0,%1,%2,%3};" \
        : "+f"((d)[0]), "+f"((d)[1]), "+f"((d)[2]), "+f"((d)[3]) \
        : "r"((a)[0]), "r"((a)[1]), "r"((a)[2]), "r"((a)[3]), \
          "r"((b)[0]), "r"((b)[1]))

#define LDSM4(r, a) \
    asm volatile("ldmatrix.sync.aligned.m8n8.x4.shared.b16 {%0,%1,%2,%3}, [%4];" \
        : "=r"((r)[0]), "=r"((r)[1]), "=r"((r)[2]), "=r"((r)[3]) : "r"(a))

__device__ __forceinline__ float fgelu(float v) {
    float z = 0.7978845608028654f * (v + 0.044715f * v * v * v);
    float e = __expf(2.0f * z);
    float t = 1.0f - 2.0f / (e + 1.0f);   // tanh(z)
    return 0.5f * v * (1.0f + t);
}

// ---------------------------------------------------------------------------
// Zero output + expert counters
// ---------------------------------------------------------------------------
__global__ void k_zero(float* __restrict__ out, int n4) {
    int i = blockIdx.x * blockDim.x + threadIdx.x;
    float4 z = make_float4(0.f, 0.f, 0.f, 0.f);
    for (int j = i; j < n4; j += gridDim.x * blockDim.x)
        ((float4*)out)[j] = z;
    if (i < NE) g_cnt[i] = 0;
}

// ---------------------------------------------------------------------------
// Transpose + convert one expert-stack of weights: [E][K][N] fp32 -> [E][N][K] fp16
// ---------------------------------------------------------------------------
__global__ void k_cvt_t(const float* __restrict__ src, __half* __restrict__ dst,
                        int K, int N) {
    __shared__ float tile[32][33];
    const int e  = blockIdx.z;
    const int nb = blockIdx.x * 32;
    const int kb = blockIdx.y * 32;
    const float* s = src + (size_t)e * K * N;
    __half* d = dst + (size_t)e * K * N;
    const int tid = threadIdx.x;   // 256
#pragma unroll
    for (int p = 0; p < 4; p++) {
        int idx = tid + p * 256;
        int r = idx >> 5, c = idx & 31;
        tile[r][c] = s[(size_t)(kb + r) * N + nb + c];
    }
    __syncthreads();
#pragma unroll
    for (int p = 0; p < 4; p++) {
        int idx = tid + p * 256;
        int r = idx >> 5, c = idx & 31;
        d[(size_t)(nb + r) * K + kb + c] = __float2half_rn(tile[c][r]);
    }
}

// ---------------------------------------------------------------------------
// Router (also writes fp16 x into g_xh)
// ---------------------------------------------------------------------------
__global__ void k_router(const float* __restrict__ x,
                         const float* __restrict__ Wr,
                         const float* __restrict__ br) {
    int warp = (blockIdx.x * blockDim.x + threadIdx.x) >> 5;
    int lane = threadIdx.x & 31;
    if (warp >= TB) return;
    const float* xr = x + (size_t)warp * HD;
    __half* gxr = g_xh + (size_t)warp * HD;

    float acc[NE];
#pragma unroll
    for (int e = 0; e < NE; e++) acc[e] = 0.f;
    for (int h = lane; h < HD; h += 32) {
        float xv = xr[h];
        gxr[h] = __float2half_rn(xv);
        float4 w0 = *(const float4*)(Wr + h * NE);
        float4 w1 = *(const float4*)(Wr + h * NE + 4);
        acc[0] += xv * w0.x; acc[1] += xv * w0.y;
        acc[2] += xv * w0.z; acc[3] += xv * w0.w;
        acc[4] += xv * w1.x; acc[5] += xv * w1.y;
        acc[6] += xv * w1.z; acc[7] += xv * w1.w;
    }
#pragma unroll
    for (int e = 0; e < NE; e++)
#pragma unroll
        for (int off = 16; off > 0; off >>= 1)
            acc[e] += __shfl_xor_sync(0xffffffffu, acc[e], off);
    if (lane == 0) {
#pragma unroll
        for (int e = 0; e < NE; e++) acc[e] += br[e];
        int i1 = 0; float l1 = acc[0];
#pragma unroll
        for (int e = 1; e < NE; e++) if (acc[e] > l1) { l1 = acc[e]; i1 = e; }
        int i2 = -1; float l2 = -3.0e38f;
#pragma unroll
        for (int e = 0; e < NE; e++) if (e != i1 && acc[e] > l2) { l2 = acc[e]; i2 = e; }
        g_p0[warp] = 1.0f / (1.0f + expf(l2 - l1));
        int p = atomicAdd(&g_cnt[i1], 1);
        g_tok[i1 * TB + p]  = warp;
        g_slot[i1 * TB + p] = 2 * warp;
        p = atomicAdd(&g_cnt[i2], 1);
        g_tok[i2 * TB + p]  = warp;
        g_slot[i2 * TB + p] = 2 * warp + 1;
    }
}

// ---------------------------------------------------------------------------
// Grouped GEMM on mma.sync fp16 (fp32 accumulate), ldmatrix fragment loads.
// 256 threads, 8 warps (2x4), warptile 64x32.
// A: [row][k] fp16 k-contiguous (g_xh or g_h). B: transposed weights [n][k] fp16.
// MODE 0: g_h[slot] = fp16(gelu(x[tok] @ W1[e] + b1[e]))        (K=HD, N over FF)
// MODE 1: out[tok] += p0 * ((g_h[slot] @ W2[e]) + b2[e]) atomic (K=FF, N over HD)
// ---------------------------------------------------------------------------
template <int MODE>
__global__ __launch_bounds__(GT, 2)
void k_gemm(const __half* __restrict__ W, const float* __restrict__ bias,
            float* __restrict__ outp) {
    constexpr int KTOT = MODE ? FF : HD;
    constexpr int LDA  = MODE ? FF : HD;
    constexpr int OROW = MODE ? HD : FF;
    constexpr int NC   = KTOT / KC;

    const int e  = blockIdx.z;
    const int me = g_cnt[e];
    const int mt = blockIdx.y;
    if (mt * BM >= me) return;
    const int ntb = blockIdx.x * BN;

    extern __shared__ char smraw[];
    char* As = smraw;
    char* Bs = smraw + B_OFF;
    int*   stok  = (int*)(smraw + LIST_OFF);
    int*   sslot = stok + 128;
    float* sp0   = (float*)(sslot + 128);

    const int tid  = threadIdx.x;
    const int wid  = tid >> 5;
    const int lane = tid & 31;
    const int wm   = wid >> 2;       // 0..1
    const int wn   = wid & 3;        // 0..3
    const int lr   = lane >> 2;      // 0..7  (groupID)
    const int lc   = lane & 3;       // 0..3  (threadID_in_group)

    if (tid < 128) {
        int i = mt * BM + tid;
        int tok = 0, slot = -1;
        if (i < me) { tok = g_tok[e * TB + i]; slot = g_slot[e * TB + i]; }
        stok[tid] = tok; sslot[tid] = slot;
        if (MODE == 1) sp0[tid] = g_p0[tok];
    }
    __syncthreads();

    // ---- cp.async mappings (256 threads, 4 segs each per tile) ----
    const int mrow = tid >> 3;            // 0..31
    const int mseg = tid & 7;             // 0..7
    const __half* Asrc = MODE ? (const __half*)g_h : (const __half*)g_xh;
    const __half* aptr[4];
#pragma unroll
    for (int m = 0; m < 4; m++) {
        int row = mrow + 32 * m;
        int rid = MODE ? sslot[row] : stok[row];
        if (rid < 0) rid = 0;
        aptr[m] = Asrc + (size_t)rid * LDA + mseg * 8;
    }
    const uint32_t asmA = smem_u32(As) + (uint32_t)(mrow * ROWB + mseg * 16);

    const __half* bglob = W + (size_t)e * HD * FF + (size_t)(ntb + mrow) * KTOT + mseg * 8;
    const uint32_t bsmB = smem_u32(Bs) + (uint32_t)(mrow * ROWB + mseg * 16);

#define LOAD_CHUNK(STG, C)                                                    \
    {                                                                         \
        uint32_t as_ = asmA + (STG) * TSTG;                                   \
        _Pragma("unroll")                                                     \
        for (int m = 0; m < 4; m++)                                           \
            cp16(as_ + m * (32 * ROWB), aptr[m] + (C) * KC);                  \
        const __half* bg = bglob + (size_t)(C) * KC;                          \
        uint32_t bs_ = bsmB + (STG) * TSTG;                                   \
        _Pragma("unroll")                                                     \
        for (int m = 0; m < 4; m++)                                           \
            cp16(bs_ + m * (32 * ROWB), bg + (size_t)m * 32 * KTOT);          \
    }

    float acc[4][4][4];
#pragma unroll
    for (int i = 0; i < 4; i++)
#pragma unroll
        for (int j = 0; j < 4; j++)
#pragma unroll
            for (int r = 0; r < 4; r++) acc[i][j][r] = 0.f;

    LOAD_CHUNK(0, 0); CP_COMMIT();
    LOAD_CHUNK(1, 1); CP_COMMIT();

    // ---- ldmatrix per-thread base addresses ----
    const uint32_t aldm = smem_u32(As) +
        (uint32_t)((wm * 64 + (lane & 15)) * ROWB + ((lane >> 4) & 1) * 16);
    const uint32_t bldm = smem_u32(Bs) +
        (uint32_t)((wn * 32 + (lane & 7) + ((lane & 16) >> 1)) * ROWB + (lane & 8) * 2);

    for (int c = 0; c < NC; c++) {
        const int pf = c + STAGES - 1;
        if (pf < NC) { LOAD_CHUNK(pf % STAGES, pf); }
        CP_COMMIT();
        CP_WAIT2();
        __syncthreads();

        const int st = c % STAGES;
        const uint32_t aS = aldm + st * TSTG;
        const uint32_t bS = bldm + st * TSTG;
#pragma unroll
        for (int k16 = 0; k16 < KC / 16; k16++) {
            const uint32_t ko = k16 * 32;    // 16 halves = 32 bytes
            uint32_t af[4][4], bf4[2][4];
#pragma unroll
            for (int i = 0; i < 4; i++)
                LDSM4(af[i], aS + i * (16 * ROWB) + ko);
#pragma unroll
            for (int jj = 0; jj < 2; jj++)
                LDSM4(bf4[jj], bS + jj * (16 * ROWB) + ko);
#pragma unroll
            for (int i = 0; i < 4; i++)
#pragma unroll
                for (int j = 0; j < 4; j++)
                    MMA_F16(acc[i][j], af[i], &bf4[j >> 1][(j & 1) * 2]);
        }
        __syncthreads();
    }

    // ---- epilogue ----
    float bv[8];
#pragma unroll
    for (int j = 0; j < 4; j++) {
        float2 t = *(const float2*)(bias + e * OROW + ntb + wn * 32 + 8 * j + lc * 2);
        bv[2 * j] = t.x; bv[2 * j + 1] = t.y;
    }

#pragma unroll
    for (int i = 0; i < 4; i++) {
        const int mr0 = wm * 64 + 16 * i + lr;
        const int s0 = sslot[mr0];
        const int s1 = sslot[mr0 + 8];
#pragma unroll
        for (int j = 0; j < 4; j++) {
            const int n = ntb + wn * 32 + 8 * j + lc * 2;
            if (MODE == 0) {
                if (s0 >= 0) {
                    *(__half2*)(g_h + (size_t)s0 * OROW + n) = __floats2half2_rn(
                        fgelu(acc[i][j][0] + bv[2 * j]),
                        fgelu(acc[i][j][1] + bv[2 * j + 1]));
                }
                if (s1 >= 0) {
                    *(__half2*)(g_h + (size_t)s1 * OROW + n) = __floats2half2_rn(
                        fgelu(acc[i][j][2] + bv[2 * j]),
                        fgelu(acc[i][j][3] + bv[2 * j + 1]));
                }
            } else {
                if (s0 >= 0) {
                    float p = sp0[mr0];
                    float* op = outp + (size_t)stok[mr0] * HD + n;
                    atomicAdd(op,     p * (acc[i][j][0] + bv[2 * j]));
                    atomicAdd(op + 1, p * (acc[i][j][1] + bv[2 * j + 1]));
                }
                if (s1 >= 0) {
                    float p = sp0[mr0 + 8];
                    float* op = outp + (size_t)stok[mr0 + 8] * HD + n;
                    atomicAdd(op,     p * (acc[i][j][2] + bv[2 * j]));
                    atomicAdd(op + 1, p * (acc[i][j][3] + bv[2 * j + 1]));
                }
            }
        }
    }
}

// ---------------------------------------------------------------------------
extern "C" void kernel_launch(void* const* d_in, const int* in_sizes, int n_in,
                              void* d_out, int out_size) {
    const float* x  = (const float*)d_in[0];
    const float* Wr = (const float*)d_in[1];
    const float* br = (const float*)d_in[2];
    const float* W1 = (const float*)d_in[3];
    const float* b1 = (const float*)d_in[4];
    const float* W2 = (const float*)d_in[5];
    const float* b2 = (const float*)d_in[6];
    float* out = (float*)d_out;

    cudaFuncSetAttribute(k_gemm<0>, cudaFuncAttributeMaxDynamicSharedMemorySize, SMEM_SZ);
    cudaFuncSetAttribute(k_gemm<1>, cudaFuncAttributeMaxDynamicSharedMemorySize, SMEM_SZ);

    __half* gw1; cudaGetSymbolAddress((void**)&gw1, g_w1h);
    __half* gw2; cudaGetSymbolAddress((void**)&gw2, g_w2h);

    k_zero<<<2048, 256>>>(out, out_size / 4);
    k_router<<<TB / 8, 256>>>(x, Wr, br);
    // W1 [K=HD][N=FF] -> [FF][HD];  W2 [K=FF][N=HD] -> [HD][FF]
    dim3 t1(FF / 32, HD / 32, NE);
    k_cvt_t<<<t1, 256>>>(W1, gw1, HD, FF);
    dim3 t2(HD / 32, FF / 32, NE);
    k_cvt_t<<<t2, 256>>>(W2, gw2, FF, HD);
    dim3 g1(FF / BN, TB / BM, NE);   // (32, 64, 8)
    k_gemm<0><<<g1, GT, SMEM_SZ>>>(gw1, b1, nullptr);
    dim3 g2(HD / BN, TB / BM, NE);   // (8, 64, 8)
    k_gemm<1><<<g2, GT, SMEM_SZ>>>(gw2, b2, out);
}

// round 15
// speedup vs baseline: 1.0649x; 1.0192x over previous
#include <cuda_runtime.h>
#include <cuda_fp16.h>
#include <cstdint>
#include <math.h>

#define TB 8192      // tokens = B*S
#define HD 1024
#define NE 8
#define FF 4096

// GEMM tiling: CTA 128x128, 8 warps (2x4), warptile 64x32, fp16 MMA k16, ldmatrix
#define GT 256       // GEMM threads per CTA
#define BM 128
#define BN 128
#define KC 64        // k-elements (halves) per chunk = 128B per row
#define STAGES 3
#define ROWB 144     // SMEM row stride bytes (128 data + 16 pad); LDSM conflict-free
#define TSTG (128 * ROWB)                 // 18432 B per tile stage
#define B_OFF (STAGES * TSTG)             // 55296
#define LIST_OFF (2 * STAGES * TSTG)      // 110592
#define SMEM_SZ (LIST_OFF + 2048)         // 112640 -> 2 CTA/SM

// ---- scratch (static device arrays; no allocation) ----
__device__ __half g_xh [(size_t)TB * HD];        // fp16 x (written by router)
__device__ __half g_h  [(size_t)2 * TB * FF];    // fp16 gelu(x@W1) per slot
__device__ __half g_w1h[(size_t)NE * FF * HD];   // W1 transposed [f][h] fp16
__device__ __half g_w2h[(size_t)NE * HD * FF];   // W2 transposed [h][f] fp16
__device__ int   g_cnt[NE];
__device__ int   g_tok[NE * TB];
__device__ int   g_slot[NE * TB];
__device__ float g_p0[TB];

// ---- helpers ----
__device__ __forceinline__ uint32_t smem_u32(const void* p) {
    uint32_t a;
    asm("{ .reg .u64 t; cvta.to.shared.u64 t, %1; cvt.u32.u64 %0, t; }" : "=r"(a) : "l"(p));
    return a;
}
__device__ __forceinline__ void cp16(uint32_t s, const void* g) {
    asm volatile("cp.async.cg.shared.global [%0], [%1], 16;" :: "r"(s), "l"(g));
}
#define CP_COMMIT() asm volatile("cp.async.commit_group;" ::: "memory")
#define CP_WAIT1()  asm volatile("cp.async.wait_group 1;" ::: "memory")

#define MMA_F16(d, a, b) \
    asm volatile("mma.sync.aligned.m16n8k16.row.col.f32.f16.f16.f32 " \
        "{%0,%1,%2,%3}, {%4,%5,%6,%7}, {%8,%9}, {%0,%1,%2,%3};" \
        : "+f"((d)[0]), "+f"((d)[1]), "+f"((d)[2]), "+f"((d)[3]) \
        : "r"((a)[0]), "r"((a)[1]), "r"((a)[2]), "r"((a)[3]), \
          "r"((b)[0]), "r"((b)[1]))

#define LDSM4(r, a) \
    asm volatile("ldmatrix.sync.aligned.m8n8.x4.shared.b16 {%0,%1,%2,%3}, [%4];" \
        : "=r"((r)[0]), "=r"((r)[1]), "=r"((r)[2]), "=r"((r)[3]) : "r"(a))

__device__ __forceinline__ float fgelu(float v) {
    float z = 0.7978845608028654f * (v + 0.044715f * v * v * v);
    float e = __expf(2.0f * z);
    float t = 1.0f - 2.0f / (e + 1.0f);   // tanh(z)
    return 0.5f * v * (1.0f + t);
}

// ---------------------------------------------------------------------------
// Zero output + expert counters
// ---------------------------------------------------------------------------
__global__ void k_zero(float* __restrict__ out, int n4) {
    int i = blockIdx.x * blockDim.x + threadIdx.x;
    float4 z = make_float4(0.f, 0.f, 0.f, 0.f);
    for (int j = i; j < n4; j += gridDim.x * blockDim.x)
        ((float4*)out)[j] = z;
    if (i < NE) g_cnt[i] = 0;
}

// ---------------------------------------------------------------------------
// Transpose + convert: [E][K][N] fp32 -> [E][N][K] fp16. 64(k) x 32(n) tiles,
// float4 reads, packed 16B fp16 writes (full sectors both directions).
// ---------------------------------------------------------------------------
__global__ void k_cvt_t(const float* __restrict__ src, __half* __restrict__ dst,
                        int K, int N) {
    __shared__ float tile[64][33];
    const int e  = blockIdx.z;
    const int nb = blockIdx.x * 32;
    const int kb = blockIdx.y * 64;
    const float* s = src + (size_t)e * K * N;
    __half* d = dst + (size_t)e * K * N;
    const int tid = threadIdx.x;   // 256

#pragma unroll
    for (int p = 0; p < 2; p++) {
        int r = (tid >> 3) + 32 * p;       // k-row 0..63
        int c = (tid & 7) * 4;             // n-col
        float4 v = *(const float4*)(s + (size_t)(kb + r) * N + nb + c);
        tile[r][c + 0] = v.x; tile[r][c + 1] = v.y;
        tile[r][c + 2] = v.z; tile[r][c + 3] = v.w;
    }
    __syncthreads();

    const int rn  = tid >> 3;              // n-row 0..31
    const int ck0 = (tid & 7) * 8;         // k-col base
    __half2 h01 = __floats2half2_rn(tile[ck0 + 0][rn], tile[ck0 + 1][rn]);
    __half2 h23 = __floats2half2_rn(tile[ck0 + 2][rn], tile[ck0 + 3][rn]);
    __half2 h45 = __floats2half2_rn(tile[ck0 + 4][rn], tile[ck0 + 5][rn]);
    __half2 h67 = __floats2half2_rn(tile[ck0 + 6][rn], tile[ck0 + 7][rn]);
    uint4 o;
    o.x = *(uint32_t*)&h01; o.y = *(uint32_t*)&h23;
    o.z = *(uint32_t*)&h45; o.w = *(uint32_t*)&h67;
    *(uint4*)(d + (size_t)(nb + rn) * K + kb + ck0) = o;
}

// ---------------------------------------------------------------------------
// Router (vectorized; also writes fp16 x into g_xh)
// ---------------------------------------------------------------------------
__global__ void k_router(const float* __restrict__ x,
                         const float* __restrict__ Wr,
                         const float* __restrict__ br) {
    int warp = (blockIdx.x * blockDim.x + threadIdx.x) >> 5;
    int lane = threadIdx.x & 31;
    if (warp >= TB) return;
    const float* xr = x + (size_t)warp * HD;
    __half* gxr = g_xh + (size_t)warp * HD;

    float acc[NE];
#pragma unroll
    for (int e = 0; e < NE; e++) acc[e] = 0.f;

    for (int h0 = lane * 4; h0 < HD; h0 += 128) {
        float4 xv = *(const float4*)(xr + h0);
        __half2 pa = __floats2half2_rn(xv.x, xv.y);
        __half2 pb = __floats2half2_rn(xv.z, xv.w);
        uint2 pk; pk.x = *(uint32_t*)&pa; pk.y = *(uint32_t*)&pb;
        *(uint2*)(gxr + h0) = pk;
        const float xs[4] = {xv.x, xv.y, xv.z, xv.w};
#pragma unroll
        for (int hh = 0; hh < 4; hh++) {
            float xvv = xs[hh];
            float4 w0 = *(const float4*)(Wr + (h0 + hh) * NE);
            float4 w1 = *(const float4*)(Wr + (h0 + hh) * NE + 4);
            acc[0] += xvv * w0.x; acc[1] += xvv * w0.y;
            acc[2] += xvv * w0.z; acc[3] += xvv * w0.w;
            acc[4] += xvv * w1.x; acc[5] += xvv * w1.y;
            acc[6] += xvv * w1.z; acc[7] += xvv * w1.w;
        }
    }
#pragma unroll
    for (int e = 0; e < NE; e++)
#pragma unroll
        for (int off = 16; off > 0; off >>= 1)
            acc[e] += __shfl_xor_sync(0xffffffffu, acc[e], off);
    if (lane == 0) {
#pragma unroll
        for (int e = 0; e < NE; e++) acc[e] += br[e];
        int i1 = 0; float l1 = acc[0];
#pragma unroll
        for (int e = 1; e < NE; e++) if (acc[e] > l1) { l1 = acc[e]; i1 = e; }
        int i2 = -1; float l2 = -3.0e38f;
#pragma unroll
        for (int e = 0; e < NE; e++) if (e != i1 && acc[e] > l2) { l2 = acc[e]; i2 = e; }
        g_p0[warp] = 1.0f / (1.0f + expf(l2 - l1));
        int p = atomicAdd(&g_cnt[i1], 1);
        g_tok[i1 * TB + p]  = warp;
        g_slot[i1 * TB + p] = 2 * warp;
        p = atomicAdd(&g_cnt[i2], 1);
        g_tok[i2 * TB + p]  = warp;
        g_slot[i2 * TB + p] = 2 * warp + 1;
    }
}

// ---------------------------------------------------------------------------
// Grouped GEMM on mma.sync fp16 (fp32 accumulate), ldmatrix fragment loads.
// 256 threads, 8 warps (2x4), warptile 64x32. ONE barrier per K-chunk.
// MODE 0: g_h[slot] = fp16(gelu(x[tok] @ W1[e] + b1[e]))        (K=HD, N over FF)
// MODE 1: out[tok] += p0 * ((g_h[slot] @ W2[e]) + b2[e]) atomic (K=FF, N over HD)
// ---------------------------------------------------------------------------
template <int MODE>
__global__ __launch_bounds__(GT, 2)
void k_gemm(const __half* __restrict__ W, const float* __restrict__ bias,
            float* __restrict__ outp) {
    constexpr int KTOT = MODE ? FF : HD;
    constexpr int LDA  = MODE ? FF : HD;
    constexpr int OROW = MODE ? HD : FF;
    constexpr int NC   = KTOT / KC;

    const int e  = blockIdx.z;
    const int me = g_cnt[e];
    const int mt = blockIdx.y;
    if (mt * BM >= me) return;
    const int ntb = blockIdx.x * BN;

    extern __shared__ char smraw[];
    char* As = smraw;
    char* Bs = smraw + B_OFF;
    int*   stok  = (int*)(smraw + LIST_OFF);
    int*   sslot = stok + 128;
    float* sp0   = (float*)(sslot + 128);

    const int tid  = threadIdx.x;
    const int wid  = tid >> 5;
    const int lane = tid & 31;
    const int wm   = wid >> 2;       // 0..1
    const int wn   = wid & 3;        // 0..3
    const int lr   = lane >> 2;      // 0..7  (groupID)
    const int lc   = lane & 3;       // 0..3  (threadID_in_group)

    if (tid < 128) {
        int i = mt * BM + tid;
        int tok = 0, slot = -1;
        if (i < me) { tok = g_tok[e * TB + i]; slot = g_slot[e * TB + i]; }
        stok[tid] = tok; sslot[tid] = slot;
        if (MODE == 1) sp0[tid] = g_p0[tok];
    }
    __syncthreads();

    // ---- cp.async mappings (256 threads, 4 segs each per tile) ----
    const int mrow = tid >> 3;            // 0..31
    const int mseg = tid & 7;             // 0..7
    const __half* Asrc = MODE ? (const __half*)g_h : (const __half*)g_xh;
    const __half* aptr[4];
#pragma unroll
    for (int m = 0; m < 4; m++) {
        int row = mrow + 32 * m;
        int rid = MODE ? sslot[row] : stok[row];
        if (rid < 0) rid = 0;
        aptr[m] = Asrc + (size_t)rid * LDA + mseg * 8;
    }
    const uint32_t asmA = smem_u32(As) + (uint32_t)(mrow * ROWB + mseg * 16);

    const __half* bglob = W + (size_t)e * HD * FF + (size_t)(ntb + mrow) * KTOT + mseg * 8;
    const uint32_t bsmB = smem_u32(Bs) + (uint32_t)(mrow * ROWB + mseg * 16);

#define LOAD_CHUNK(STG, C)                                                    \
    {                                                                         \
        uint32_t as_ = asmA + (STG) * TSTG;                                   \
        _Pragma("unroll")                                                     \
        for (int m = 0; m < 4; m++)                                           \
            cp16(as_ + m * (32 * ROWB), aptr[m] + (C) * KC);                  \
        const __half* bg = bglob + (size_t)(C) * KC;                          \
        uint32_t bs_ = bsmB + (STG) * TSTG;                                   \
        _Pragma("unroll")                                                     \
        for (int m = 0; m < 4; m++)                                           \
            cp16(bs_ + m * (32 * ROWB), bg + (size_t)m * 32 * KTOT);          \
    }

    float acc[4][4][4];
#pragma unroll
    for (int i = 0; i < 4; i++)
#pragma unroll
        for (int j = 0; j < 4; j++)
#pragma unroll
            for (int r = 0; r < 4; r++) acc[i][j][r] = 0.f;

    LOAD_CHUNK(0, 0); CP_COMMIT();
    LOAD_CHUNK(1, 1); CP_COMMIT();

    // ---- ldmatrix per-thread base addresses ----
    const uint32_t aldm = smem_u32(As) +
        (uint32_t)((wm * 64 + (lane & 15)) * ROWB + ((lane >> 4) & 1) * 16);
    const uint32_t bldm = smem_u32(Bs) +
        (uint32_t)((wn * 32 + (lane & 7) + ((lane & 16) >> 1)) * ROWB + (lane & 8) * 2);

    for (int c = 0; c < NC; c++) {
        // wait for chunk c, one barrier, then issue loads for c+2
        CP_WAIT1();
        __syncthreads();
        const int pf = c + STAGES - 1;
        if (pf < NC) { LOAD_CHUNK(pf % STAGES, pf); }
        CP_COMMIT();

        const int st = c % STAGES;
        const uint32_t aS = aldm + st * TSTG;
        const uint32_t bS = bldm + st * TSTG;
#pragma unroll
        for (int k16 = 0; k16 < KC / 16; k16++) {
            const uint32_t ko = k16 * 32;    // 16 halves = 32 bytes
            uint32_t af[4][4], bf4[2][4];
#pragma unroll
            for (int i = 0; i < 4; i++)
                LDSM4(af[i], aS + i * (16 * ROWB) + ko);
#pragma unroll
            for (int jj = 0; jj < 2; jj++)
                LDSM4(bf4[jj], bS + jj * (16 * ROWB) + ko);
#pragma unroll
            for (int i = 0; i < 4; i++)
#pragma unroll
                for (int j = 0; j < 4; j++)
                    MMA_F16(acc[i][j], af[i], &bf4[j >> 1][(j & 1) * 2]);
        }
    }

    // ---- epilogue ----
    float bv[8];
#pragma unroll
    for (int j = 0; j < 4; j++) {
        float2 t = *(const float2*)(bias + e * OROW + ntb + wn * 32 + 8 * j + lc * 2);
        bv[2 * j] = t.x; bv[2 * j + 1] = t.y;
    }

#pragma unroll
    for (int i = 0; i < 4; i++) {
        const int mr0 = wm * 64 + 16 * i + lr;
        const int s0 = sslot[mr0];
        const int s1 = sslot[mr0 + 8];
#pragma unroll
        for (int j = 0; j < 4; j++) {
            const int n = ntb + wn * 32 + 8 * j + lc * 2;
            if (MODE == 0) {
                if (s0 >= 0) {
                    *(__half2*)(g_h + (size_t)s0 * OROW + n) = __floats2half2_rn(
                        fgelu(acc[i][j][0] + bv[2 * j]),
                        fgelu(acc[i][j][1] + bv[2 * j + 1]));
                }
                if (s1 >= 0) {
                    *(__half2*)(g_h + (size_t)s1 * OROW + n) = __floats2half2_rn(
                        fgelu(acc[i][j][2] + bv[2 * j]),
                        fgelu(acc[i][j][3] + bv[2 * j + 1]));
                }
            } else {
                if (s0 >= 0) {
                    float p = sp0[mr0];
                    float* op = outp + (size_t)stok[mr0] * HD + n;
                    atomicAdd(op,     p * (acc[i][j][0] + bv[2 * j]));
                    atomicAdd(op + 1, p * (acc[i][j][1] + bv[2 * j + 1]));
                }
                if (s1 >= 0) {
                    float p = sp0[mr0 + 8];
                    float* op = outp + (size_t)stok[mr0 + 8] * HD + n;
                    atomicAdd(op,     p * (acc[i][j][2] + bv[2 * j]));
                    atomicAdd(op + 1, p * (acc[i][j][3] + bv[2 * j + 1]));
                }
            }
        }
    }
}

// ---------------------------------------------------------------------------
extern "C" void kernel_launch(void* const* d_in, const int* in_sizes, int n_in,
                              void* d_out, int out_size) {
    const float* x  = (const float*)d_in[0];
    const float* Wr = (const float*)d_in[1];
    const float* br = (const float*)d_in[2];
    const float* W1 = (const float*)d_in[3];
    const float* b1 = (const float*)d_in[4];
    const float* W2 = (const float*)d_in[5];
    const float* b2 = (const float*)d_in[6];
    float* out = (float*)d_out;

    cudaFuncSetAttribute(k_gemm<0>, cudaFuncAttributeMaxDynamicSharedMemorySize, SMEM_SZ);
    cudaFuncSetAttribute(k_gemm<1>, cudaFuncAttributeMaxDynamicSharedMemorySize, SMEM_SZ);

    __half* gw1; cudaGetSymbolAddress((void**)&gw1, g_w1h);
    __half* gw2; cudaGetSymbolAddress((void**)&gw2, g_w2h);

    k_zero<<<2048, 256>>>(out, out_size / 4);
    k_router<<<TB / 8, 256>>>(x, Wr, br);
    // W1 [K=HD][N=FF] -> [FF][HD];  W2 [K=FF][N=HD] -> [HD][FF]
    dim3 t1(FF / 32, HD / 64, NE);   // (128, 16, 8)
    k_cvt_t<<<t1, 256>>>(W1, gw1, HD, FF);
    dim3 t2(HD / 32, FF / 64, NE);   // (32, 64, 8)
    k_cvt_t<<<t2, 256>>>(W2, gw2, FF, HD);
    dim3 g1(FF / BN, TB / BM, NE);   // (32, 64, 8)
    k_gemm<0><<<g1, GT, SMEM_SZ>>>(gw1, b1, nullptr);
    dim3 g2(HD / BN, TB / BM, NE);   // (8, 64, 8)
    k_gemm<1><<<g2, GT, SMEM_SZ>>>(gw2, b2, out);
}

// round 16
// speedup vs baseline: 1.0671x; 1.0020x over previous
#include <cuda_runtime.h>
#include <cuda_fp16.h>
#include <cstdint>
#include <math.h>

#define TB 8192      // tokens = B*S
#define HD 1024
#define NE 8
#define FF 4096

// GEMM tiling: CTA 128x128, 8 warps (2x4), warptile 64x32, fp16 MMA k16, ldmatrix
#define GT 256       // GEMM threads per CTA
#define BM 128
#define BN 128
#define KC 64        // k-elements (halves) per chunk = 128B per row
#define STAGES 3
#define ROWB 144     // SMEM row stride bytes (128 data + 16 pad); LDSM conflict-free
#define TSTG (128 * ROWB)                 // 18432 B per tile stage
#define B_OFF (STAGES * TSTG)             // 55296
#define LIST_OFF (2 * STAGES * TSTG)      // 110592
#define SMEM_SZ (LIST_OFF + 2048)         // 112640 -> 2 CTA/SM

// ---- scratch (static device arrays; no allocation) ----
__device__ __half g_xh [(size_t)TB * HD];        // fp16 x (written by router)
__device__ __half g_h  [(size_t)2 * TB * FF];    // fp16 gelu(x@W1) per slot
__device__ __half g_w1h[(size_t)NE * FF * HD];   // W1 transposed [f][h] fp16
__device__ __half g_w2h[(size_t)NE * HD * FF];   // W2 transposed [h][f] fp16
__device__ int   g_cnt[NE];
__device__ int   g_tok[NE * TB];
__device__ int   g_slot[NE * TB];
__device__ float g_p0[TB];

// ---- helpers ----
__device__ __forceinline__ uint32_t smem_u32(const void* p) {
    uint32_t a;
    asm("{ .reg .u64 t; cvta.to.shared.u64 t, %1; cvt.u32.u64 %0, t; }" : "=r"(a) : "l"(p));
    return a;
}
__device__ __forceinline__ void cp16(uint32_t s, const void* g) {
    asm volatile("cp.async.cg.shared.global [%0], [%1], 16;" :: "r"(s), "l"(g));
}
#define CP_COMMIT() asm volatile("cp.async.commit_group;" ::: "memory")
#define CP_WAIT1()  asm volatile("cp.async.wait_group 1;" ::: "memory")

#define MMA_F16(d, a, b) \
    asm volatile("mma.sync.aligned.m16n8k16.row.col.f32.f16.f16.f32 " \
        "{%0,%1,%2,%3}, {%4,%5,%6,%7}, {%8,%9}, {%0,%1,%2,%3};" \
        : "+f"((d)[0]), "+f"((d)[1]), "+f"((d)[2]), "+f"((d)[3]) \
        : "r"((a)[0]), "r"((a)[1]), "r"((a)[2]), "r"((a)[3]), \
          "r"((b)[0]), "r"((b)[1]))

#define LDSM4(r, a) \
    asm volatile("ldmatrix.sync.aligned.m8n8.x4.shared.b16 {%0,%1,%2,%3}, [%4];" \
        : "=r"((r)[0]), "=r"((r)[1]), "=r"((r)[2]), "=r"((r)[3]) : "r"(a))

__device__ __forceinline__ float fgelu(float v) {
    float z = 0.7978845608028654f * (v + 0.044715f * v * v * v);
    float e = __expf(2.0f * z);
    float t = 1.0f - 2.0f / (e + 1.0f);   // tanh(z)
    return 0.5f * v * (1.0f + t);
}

// ---------------------------------------------------------------------------
// Zero output + expert counters
// ---------------------------------------------------------------------------
__global__ void k_zero(float* __restrict__ out, int n4) {
    int i = blockIdx.x * blockDim.x + threadIdx.x;
    float4 z = make_float4(0.f, 0.f, 0.f, 0.f);
    for (int j = i; j < n4; j += gridDim.x * blockDim.x)
        ((float4*)out)[j] = z;
    if (i < NE) g_cnt[i] = 0;
}

// ---------------------------------------------------------------------------
// Transpose + convert: [E][K][N] fp32 -> [E][N][K] fp16. 64(k) x 32(n) tiles,
// float4 reads, packed 16B fp16 writes (full sectors both directions).
// ---------------------------------------------------------------------------
__global__ void k_cvt_t(const float* __restrict__ src, __half* __restrict__ dst,
                        int K, int N) {
    __shared__ float tile[64][33];
    const int e  = blockIdx.z;
    const int nb = blockIdx.x * 32;
    const int kb = blockIdx.y * 64;
    const float* s = src + (size_t)e * K * N;
    __half* d = dst + (size_t)e * K * N;
    const int tid = threadIdx.x;   // 256

#pragma unroll
    for (int p = 0; p < 2; p++) {
        int r = (tid >> 3) + 32 * p;       // k-row 0..63
        int c = (tid & 7) * 4;             // n-col
        float4 v = *(const float4*)(s + (size_t)(kb + r) * N + nb + c);
        tile[r][c + 0] = v.x; tile[r][c + 1] = v.y;
        tile[r][c + 2] = v.z; tile[r][c + 3] = v.w;
    }
    __syncthreads();

    const int rn  = tid >> 3;              // n-row 0..31
    const int ck0 = (tid & 7) * 8;         // k-col base
    __half2 h01 = __floats2half2_rn(tile[ck0 + 0][rn], tile[ck0 + 1][rn]);
    __half2 h23 = __floats2half2_rn(tile[ck0 + 2][rn], tile[ck0 + 3][rn]);
    __half2 h45 = __floats2half2_rn(tile[ck0 + 4][rn], tile[ck0 + 5][rn]);
    __half2 h67 = __floats2half2_rn(tile[ck0 + 6][rn], tile[ck0 + 7][rn]);
    uint4 o;
    o.x = *(uint32_t*)&h01; o.y = *(uint32_t*)&h23;
    o.z = *(uint32_t*)&h45; o.w = *(uint32_t*)&h67;
    *(uint4*)(d + (size_t)(nb + rn) * K + kb + ck0) = o;
}

// ---------------------------------------------------------------------------
// Router (vectorized; also writes fp16 x into g_xh)
// ---------------------------------------------------------------------------
__global__ void k_router(const float* __restrict__ x,
                         const float* __restrict__ Wr,
                         const float* __restrict__ br) {
    int warp = (blockIdx.x * blockDim.x + threadIdx.x) >> 5;
    int lane = threadIdx.x & 31;
    if (warp >= TB) return;
    const float* xr = x + (size_t)warp * HD;
    __half* gxr = g_xh + (size_t)warp * HD;

    float acc[NE];
#pragma unroll
    for (int e = 0; e < NE; e++) acc[e] = 0.f;

    for (int h0 = lane * 4; h0 < HD; h0 += 128) {
        float4 xv = *(const float4*)(xr + h0);
        __half2 pa = __floats2half2_rn(xv.x, xv.y);
        __half2 pb = __floats2half2_rn(xv.z, xv.w);
        uint2 pk; pk.x = *(uint32_t*)&pa; pk.y = *(uint32_t*)&pb;
        *(uint2*)(gxr + h0) = pk;
        const float xs[4] = {xv.x, xv.y, xv.z, xv.w};
#pragma unroll
        for (int hh = 0; hh < 4; hh++) {
            float xvv = xs[hh];
            float4 w0 = *(const float4*)(Wr + (h0 + hh) * NE);
            float4 w1 = *(const float4*)(Wr + (h0 + hh) * NE + 4);
            acc[0] += xvv * w0.x; acc[1] += xvv * w0.y;
            acc[2] += xvv * w0.z; acc[3] += xvv * w0.w;
            acc[4] += xvv * w1.x; acc[5] += xvv * w1.y;
            acc[6] += xvv * w1.z; acc[7] += xvv * w1.w;
        }
    }
#pragma unroll
    for (int e = 0; e < NE; e++)
#pragma unroll
        for (int off = 16; off > 0; off >>= 1)
            acc[e] += __shfl_xor_sync(0xffffffffu, acc[e], off);
    if (lane == 0) {
#pragma unroll
        for (int e = 0; e < NE; e++) acc[e] += br[e];
        int i1 = 0; float l1 = acc[0];
#pragma unroll
        for (int e = 1; e < NE; e++) if (acc[e] > l1) { l1 = acc[e]; i1 = e; }
        int i2 = -1; float l2 = -3.0e38f;
#pragma unroll
        for (int e = 0; e < NE; e++) if (e != i1 && acc[e] > l2) { l2 = acc[e]; i2 = e; }
        g_p0[warp] = 1.0f / (1.0f + expf(l2 - l1));
        int p = atomicAdd(&g_cnt[i1], 1);
        g_tok[i1 * TB + p]  = warp;
        g_slot[i1 * TB + p] = 2 * warp;
        p = atomicAdd(&g_cnt[i2], 1);
        g_tok[i2 * TB + p]  = warp;
        g_slot[i2 * TB + p] = 2 * warp + 1;
    }
}

// ---------------------------------------------------------------------------
// Grouped GEMM on mma.sync fp16 (fp32 accumulate), ldmatrix fragment loads.
// 256 threads, 8 warps (2x4), warptile 64x32. ONE barrier per K-chunk.
// MODE 0: g_h[slot] = fp16(gelu(x[tok] @ W1[e] + b1[e]))        (K=HD, N over FF)
// MODE 1: out[tok] += p0 * ((g_h[slot] @ W2[e]) + b2[e]) atomic (K=FF, N over HD)
// ---------------------------------------------------------------------------
template <int MODE>
__global__ __launch_bounds__(GT, 2)
void k_gemm(const __half* __restrict__ W, const float* __restrict__ bias,
            float* __restrict__ outp) {
    constexpr int KTOT = MODE ? FF : HD;
    constexpr int LDA  = MODE ? FF : HD;
    constexpr int OROW = MODE ? HD : FF;
    constexpr int NC   = KTOT / KC;

    const int e  = blockIdx.z;
    const int me = g_cnt[e];
    const int mt = blockIdx.y;
    if (mt * BM >= me) return;
    const int ntb = blockIdx.x * BN;

    extern __shared__ char smraw[];
    char* As = smraw;
    char* Bs = smraw + B_OFF;
    int*   stok  = (int*)(smraw + LIST_OFF);
    int*   sslot = stok + 128;
    float* sp0   = (float*)(sslot + 128);

    const int tid  = threadIdx.x;
    const int wid  = tid >> 5;
    const int lane = tid & 31;
    const int wm   = wid >> 2;       // 0..1
    const int wn   = wid & 3;        // 0..3
    const int lr   = lane >> 2;      // 0..7  (groupID)
    const int lc   = lane & 3;       // 0..3  (threadID_in_group)

    if (tid < 128) {
        int i = mt * BM + tid;
        int tok = 0, slot = -1;
        if (i < me) { tok = g_tok[e * TB + i]; slot = g_slot[e * TB + i]; }
        stok[tid] = tok; sslot[tid] = slot;
        if (MODE == 1) sp0[tid] = g_p0[tok];
    }
    __syncthreads();

    // ---- cp.async mappings (256 threads, 4 segs each per tile) ----
    const int mrow = tid >> 3;            // 0..31
    const int mseg = tid & 7;             // 0..7
    const __half* Asrc = MODE ? (const __half*)g_h : (const __half*)g_xh;
    const __half* aptr[4];
#pragma unroll
    for (int m = 0; m < 4; m++) {
        int row = mrow + 32 * m;
        int rid = MODE ? sslot[row] : stok[row];
        if (rid < 0) rid = 0;
        aptr[m] = Asrc + (size_t)rid * LDA + mseg * 8;
    }
    const uint32_t asmA = smem_u32(As) + (uint32_t)(mrow * ROWB + mseg * 16);

    const __half* bglob = W + (size_t)e * HD * FF + (size_t)(ntb + mrow) * KTOT + mseg * 8;
    const uint32_t bsmB = smem_u32(Bs) + (uint32_t)(mrow * ROWB + mseg * 16);

#define LOAD_CHUNK(STG, C)                                                    \
    {                                                                         \
        uint32_t as_ = asmA + (STG) * TSTG;                                   \
        _Pragma("unroll")                                                     \
        for (int m = 0; m < 4; m++)                                           \
            cp16(as_ + m * (32 * ROWB), aptr[m] + (C) * KC);                  \
        const __half* bg = bglob + (size_t)(C) * KC;                          \
        uint32_t bs_ = bsmB + (STG) * TSTG;                                   \
        _Pragma("unroll")                                                     \
        for (int m = 0; m < 4; m++)                                           \
            cp16(bs_ + m * (32 * ROWB), bg + (size_t)m * 32 * KTOT);          \
    }

    float acc[4][4][4];
#pragma unroll
    for (int i = 0; i < 4; i++)
#pragma unroll
        for (int j = 0; j < 4; j++)
#pragma unroll
            for (int r = 0; r < 4; r++) acc[i][j][r] = 0.f;

    LOAD_CHUNK(0, 0); CP_COMMIT();
    LOAD_CHUNK(1, 1); CP_COMMIT();

    // ---- ldmatrix per-thread base addresses ----
    const uint32_t aldm = smem_u32(As) +
        (uint32_t)((wm * 64 + (lane & 15)) * ROWB + ((lane >> 4) & 1) * 16);
    const uint32_t bldm = smem_u32(Bs) +
        (uint32_t)((wn * 32 + (lane & 7) + ((lane & 16) >> 1)) * ROWB + (lane & 8) * 2);

    for (int c = 0; c < NC; c++) {
        // wait for chunk c, one barrier, then issue loads for c+2
        CP_WAIT1();
        __syncthreads();
        const int pf = c + STAGES - 1;
        if (pf < NC) { LOAD_CHUNK(pf % STAGES, pf); }
        CP_COMMIT();

        const int st = c % STAGES;
        const uint32_t aS = aldm + st * TSTG;
        const uint32_t bS = bldm + st * TSTG;
#pragma unroll
        for (int k16 = 0; k16 < KC / 16; k16++) {
            const uint32_t ko = k16 * 32;    // 16 halves = 32 bytes
            uint32_t af[4][4], bf4[2][4];
#pragma unroll
            for (int i = 0; i < 4; i++)
                LDSM4(af[i], aS + i * (16 * ROWB) + ko);
#pragma unroll
            for (int jj = 0; jj < 2; jj++)
                LDSM4(bf4[jj], bS + jj * (16 * ROWB) + ko);
#pragma unroll
            for (int i = 0; i < 4; i++)
#pragma unroll
                for (int j = 0; j < 4; j++)
                    MMA_F16(acc[i][j], af[i], &bf4[j >> 1][(j & 1) * 2]);
        }
    }

    // ---- epilogue ----
    float bv[8];
#pragma unroll
    for (int j = 0; j < 4; j++) {
        float2 t = *(const float2*)(bias + e * OROW + ntb + wn * 32 + 8 * j + lc * 2);
        bv[2 * j] = t.x; bv[2 * j + 1] = t.y;
    }

#pragma unroll
    for (int i = 0; i < 4; i++) {
        const int mr0 = wm * 64 + 16 * i + lr;
        const int s0 = sslot[mr0];
        const int s1 = sslot[mr0 + 8];
#pragma unroll
        for (int j = 0; j < 4; j++) {
            const int n = ntb + wn * 32 + 8 * j + lc * 2;
            if (MODE == 0) {
                if (s0 >= 0) {
                    *(__half2*)(g_h + (size_t)s0 * OROW + n) = __floats2half2_rn(
                        fgelu(acc[i][j][0] + bv[2 * j]),
                        fgelu(acc[i][j][1] + bv[2 * j + 1]));
                }
                if (s1 >= 0) {
                    *(__half2*)(g_h + (size_t)s1 * OROW + n) = __floats2half2_rn(
                        fgelu(acc[i][j][2] + bv[2 * j]),
                        fgelu(acc[i][j][3] + bv[2 * j + 1]));
                }
            } else {
                if (s0 >= 0) {
                    float p = sp0[mr0];
                    float* op = outp + (size_t)stok[mr0] * HD + n;
                    atomicAdd(op,     p * (acc[i][j][0] + bv[2 * j]));
                    atomicAdd(op + 1, p * (acc[i][j][1] + bv[2 * j + 1]));
                }
                if (s1 >= 0) {
                    float p = sp0[mr0 + 8];
                    float* op = outp + (size_t)stok[mr0 + 8] * HD + n;
                    atomicAdd(op,     p * (acc[i][j][2] + bv[2 * j]));
                    atomicAdd(op + 1, p * (acc[i][j][3] + bv[2 * j + 1]));
                }
            }
        }
    }
}

// ---------------------------------------------------------------------------
extern "C" void kernel_launch(void* const* d_in, const int* in_sizes, int n_in,
                              void* d_out, int out_size) {
    const float* x  = (const float*)d_in[0];
    const float* Wr = (const float*)d_in[1];
    const float* br = (const float*)d_in[2];
    const float* W1 = (const float*)d_in[3];
    const float* b1 = (const float*)d_in[4];
    const float* W2 = (const float*)d_in[5];
    const float* b2 = (const float*)d_in[6];
    float* out = (float*)d_out;

    // one-time resource setup (before first capture; replayed graph sees only
    // the recorded kernel launches + event edges)
    static bool init_done = false;
    static cudaStream_t s1, s2;
    static cudaEvent_t ev_root, ev1, ev2;
    if (!init_done) {
        cudaStreamCreateWithFlags(&s1, cudaStreamNonBlocking);
        cudaStreamCreateWithFlags(&s2, cudaStreamNonBlocking);
        cudaEventCreateWithFlags(&ev_root, cudaEventDisableTiming);
        cudaEventCreateWithFlags(&ev1, cudaEventDisableTiming);
        cudaEventCreateWithFlags(&ev2, cudaEventDisableTiming);
        cudaFuncSetAttribute(k_gemm<0>, cudaFuncAttributeMaxDynamicSharedMemorySize, SMEM_SZ);
        cudaFuncSetAttribute(k_gemm<1>, cudaFuncAttributeMaxDynamicSharedMemorySize, SMEM_SZ);
        init_done = true;
    }

    __half* gw1; cudaGetSymbolAddress((void**)&gw1, g_w1h);
    __half* gw2; cudaGetSymbolAddress((void**)&gw2, g_w2h);

    // fork: cvt kernels run on side streams, concurrent with zero+router
    cudaEventRecord(ev_root, 0);
    cudaStreamWaitEvent(s1, ev_root, 0);
    cudaStreamWaitEvent(s2, ev_root, 0);

    dim3 t1(FF / 32, HD / 64, NE);   // W1 [HD][FF] -> [FF][HD]
    k_cvt_t<<<t1, 256, 0, s1>>>(W1, gw1, HD, FF);
    cudaEventRecord(ev1, s1);
    dim3 t2(HD / 32, FF / 64, NE);   // W2 [FF][HD] -> [HD][FF]
    k_cvt_t<<<t2, 256, 0, s2>>>(W2, gw2, FF, HD);
    cudaEventRecord(ev2, s2);

    k_zero<<<2048, 256>>>(out, out_size / 4);
    k_router<<<TB / 8, 256>>>(x, Wr, br);

    // join: GEMM1 needs router + cvt(W1); GEMM2 additionally needs cvt(W2)
    cudaStreamWaitEvent(0, ev1, 0);
    dim3 g1(FF / BN, TB / BM, NE);   // (32, 64, 8)
    k_gemm<0><<<g1, GT, SMEM_SZ>>>(gw1, b1, nullptr);
    cudaStreamWaitEvent(0, ev2, 0);
    dim3 g2(HD / BN, TB / BM, NE);   // (8, 64, 8)
    k_gemm<1><<<g2, GT, SMEM_SZ>>>(gw2, b2, out);
}

// round 17
// speedup vs baseline: 1.0716x; 1.0042x over previous
#include <cuda_runtime.h>
#include <cuda_fp16.h>
#include <cstdint>
#include <math.h>

#define TB 8192      // tokens = B*S
#define HD 1024
#define NE 8
#define FF 4096

// GEMM tiling: CTA 128x128, 8 warps (2x4), warptile 64x32, fp16 MMA k16, ldmatrix
#define GT 256       // GEMM threads per CTA
#define BM 128
#define BN 128
#define KC 64        // k-elements (halves) per chunk = 128B per row
#define STAGES 3
#define ROWB 144     // SMEM row stride bytes (128 data + 16 pad); LDSM conflict-free
#define TSTG (128 * ROWB)                 // 18432 B per tile stage
#define B_OFF (STAGES * TSTG)             // 55296
#define LIST_OFF (2 * STAGES * TSTG)      // 110592
#define SMEM_SZ (LIST_OFF + 2048)         // 112640 -> 2 CTA/SM

// ---- scratch (static device arrays; no allocation) ----
__device__ __half g_xh [(size_t)TB * HD];        // fp16 x (written by router)
__device__ __half g_h  [(size_t)2 * TB * FF];    // fp16 gelu(x@W1) per slot
__device__ __half g_w1h[(size_t)NE * FF * HD];   // W1 transposed [f][h] fp16
__device__ __half g_w2h[(size_t)NE * HD * FF];   // W2 transposed [h][f] fp16
__device__ int   g_cnt[NE];
__device__ int   g_tok[NE * TB];
__device__ int   g_slot[NE * TB];
__device__ float g_p0[TB];

// ---- helpers ----
__device__ __forceinline__ uint32_t smem_u32(const void* p) {
    uint32_t a;
    asm("{ .reg .u64 t; cvta.to.shared.u64 t, %1; cvt.u32.u64 %0, t; }" : "=r"(a) : "l"(p));
    return a;
}
__device__ __forceinline__ void cp16(uint32_t s, const void* g) {
    asm volatile("cp.async.cg.shared.global [%0], [%1], 16;" :: "r"(s), "l"(g));
}
#define CP_COMMIT() asm volatile("cp.async.commit_group;" ::: "memory")
#define CP_WAIT1()  asm volatile("cp.async.wait_group 1;" ::: "memory")

#define MMA_F16(d, a, b) \
    asm volatile("mma.sync.aligned.m16n8k16.row.col.f32.f16.f16.f32 " \
        "{%0,%1,%2,%3}, {%4,%5,%6,%7}, {%8,%9}, {%0,%1,%2,%3};" \
        : "+f"((d)[0]), "+f"((d)[1]), "+f"((d)[2]), "+f"((d)[3]) \
        : "r"((a)[0]), "r"((a)[1]), "r"((a)[2]), "r"((a)[3]), \
          "r"((b)[0]), "r"((b)[1]))

#define LDSM4(r, a) \
    asm volatile("ldmatrix.sync.aligned.m8n8.x4.shared.b16 {%0,%1,%2,%3}, [%4];" \
        : "=r"((r)[0]), "=r"((r)[1]), "=r"((r)[2]), "=r"((r)[3]) : "r"(a))

__device__ __forceinline__ float fgelu(float v) {
    float z = 0.7978845608028654f * (v + 0.044715f * v * v * v);
    float e = __expf(2.0f * z);
    float t = 1.0f - 2.0f / (e + 1.0f);   // tanh(z)
    return 0.5f * v * (1.0f + t);
}

// ---------------------------------------------------------------------------
// Zero output + expert-counter init handled in router block 0 alternative:
// counters cleared here too (zero runs on a side stream before router join? no:
// router needs g_cnt cleared). Keep counters in a separate tiny kernel on the
// router stream; the big out-zero rides the side stream.
// ---------------------------------------------------------------------------
__global__ void k_cnt0() {
    if (threadIdx.x < NE) g_cnt[threadIdx.x] = 0;
}
__global__ void k_zero(float* __restrict__ out, int n4) {
    int i = blockIdx.x * blockDim.x + threadIdx.x;
    float4 z = make_float4(0.f, 0.f, 0.f, 0.f);
    for (int j = i; j < n4; j += gridDim.x * blockDim.x)
        ((float4*)out)[j] = z;
}

// ---------------------------------------------------------------------------
// Transpose + convert: [E][K][N] fp32 -> [E][N][K] fp16. 64(k) x 32(n) tiles,
// float4 reads, packed 16B fp16 writes (full sectors both directions).
// ---------------------------------------------------------------------------
__global__ void k_cvt_t(const float* __restrict__ src, __half* __restrict__ dst,
                        int K, int N) {
    __shared__ float tile[64][33];
    const int e  = blockIdx.z;
    const int nb = blockIdx.x * 32;
    const int kb = blockIdx.y * 64;
    const float* s = src + (size_t)e * K * N;
    __half* d = dst + (size_t)e * K * N;
    const int tid = threadIdx.x;   // 256

#pragma unroll
    for (int p = 0; p < 2; p++) {
        int r = (tid >> 3) + 32 * p;       // k-row 0..63
        int c = (tid & 7) * 4;             // n-col
        float4 v = *(const float4*)(s + (size_t)(kb + r) * N + nb + c);
        tile[r][c + 0] = v.x; tile[r][c + 1] = v.y;
        tile[r][c + 2] = v.z; tile[r][c + 3] = v.w;
    }
    __syncthreads();

    const int rn  = tid >> 3;              // n-row 0..31
    const int ck0 = (tid & 7) * 8;         // k-col base
    __half2 h01 = __floats2half2_rn(tile[ck0 + 0][rn], tile[ck0 + 1][rn]);
    __half2 h23 = __floats2half2_rn(tile[ck0 + 2][rn], tile[ck0 + 3][rn]);
    __half2 h45 = __floats2half2_rn(tile[ck0 + 4][rn], tile[ck0 + 5][rn]);
    __half2 h67 = __floats2half2_rn(tile[ck0 + 6][rn], tile[ck0 + 7][rn]);
    uint4 o;
    o.x = *(uint32_t*)&h01; o.y = *(uint32_t*)&h23;
    o.z = *(uint32_t*)&h45; o.w = *(uint32_t*)&h67;
    *(uint4*)(d + (size_t)(nb + rn) * K + kb + ck0) = o;
}

// ---------------------------------------------------------------------------
// Router: front-batched x loads (MLP=8), identical accumulation order.
// Also writes fp16 x into g_xh.
// ---------------------------------------------------------------------------
__global__ void k_router(const float* __restrict__ x,
                         const float* __restrict__ Wr,
                         const float* __restrict__ br) {
    int warp = (blockIdx.x * blockDim.x + threadIdx.x) >> 5;
    int lane = threadIdx.x & 31;
    if (warp >= TB) return;
    const float* xr = x + (size_t)warp * HD;
    __half* gxr = g_xh + (size_t)warp * HD;

    // batch all 8 x-loads (independent -> 8 DRAM requests in flight)
    float4 xv[8];
#pragma unroll
    for (int i = 0; i < 8; i++)
        xv[i] = *(const float4*)(xr + lane * 4 + i * 128);

    // fp16 stores
#pragma unroll
    for (int i = 0; i < 8; i++) {
        __half2 pa = __floats2half2_rn(xv[i].x, xv[i].y);
        __half2 pb = __floats2half2_rn(xv[i].z, xv[i].w);
        uint2 pk; pk.x = *(uint32_t*)&pa; pk.y = *(uint32_t*)&pb;
        *(uint2*)(gxr + lane * 4 + i * 128) = pk;
    }

    float acc[NE];
#pragma unroll
    for (int e = 0; e < NE; e++) acc[e] = 0.f;

#pragma unroll
    for (int i = 0; i < 8; i++) {
        const int h0 = lane * 4 + i * 128;
        const float xs[4] = {xv[i].x, xv[i].y, xv[i].z, xv[i].w};
#pragma unroll
        for (int hh = 0; hh < 4; hh++) {
            float xvv = xs[hh];
            float4 w0 = *(const float4*)(Wr + (h0 + hh) * NE);
            float4 w1 = *(const float4*)(Wr + (h0 + hh) * NE + 4);
            acc[0] += xvv * w0.x; acc[1] += xvv * w0.y;
            acc[2] += xvv * w0.z; acc[3] += xvv * w0.w;
            acc[4] += xvv * w1.x; acc[5] += xvv * w1.y;
            acc[6] += xvv * w1.z; acc[7] += xvv * w1.w;
        }
    }
#pragma unroll
    for (int e = 0; e < NE; e++)
#pragma unroll
        for (int off = 16; off > 0; off >>= 1)
            acc[e] += __shfl_xor_sync(0xffffffffu, acc[e], off);
    if (lane == 0) {
#pragma unroll
        for (int e = 0; e < NE; e++) acc[e] += br[e];
        int i1 = 0; float l1 = acc[0];
#pragma unroll
        for (int e = 1; e < NE; e++) if (acc[e] > l1) { l1 = acc[e]; i1 = e; }
        int i2 = -1; float l2 = -3.0e38f;
#pragma unroll
        for (int e = 0; e < NE; e++) if (e != i1 && acc[e] > l2) { l2 = acc[e]; i2 = e; }
        g_p0[warp] = 1.0f / (1.0f + expf(l2 - l1));
        int p = atomicAdd(&g_cnt[i1], 1);
        g_tok[i1 * TB + p]  = warp;
        g_slot[i1 * TB + p] = 2 * warp;
        p = atomicAdd(&g_cnt[i2], 1);
        g_tok[i2 * TB + p]  = warp;
        g_slot[i2 * TB + p] = 2 * warp + 1;
    }
}

// ---------------------------------------------------------------------------
// Grouped GEMM on mma.sync fp16 (fp32 accumulate), ldmatrix fragment loads.
// 256 threads, 8 warps (2x4), warptile 64x32. ONE barrier per K-chunk.
// MODE 0: g_h[slot] = fp16(gelu(x[tok] @ W1[e] + b1[e]))        (K=HD, N over FF)
// MODE 1: out[tok] += p0 * ((g_h[slot] @ W2[e]) + b2[e]) atomic (K=FF, N over HD)
// ---------------------------------------------------------------------------
template <int MODE>
__global__ __launch_bounds__(GT, 2)
void k_gemm(const __half* __restrict__ W, const float* __restrict__ bias,
            float* __restrict__ outp) {
    constexpr int KTOT = MODE ? FF : HD;
    constexpr int LDA  = MODE ? FF : HD;
    constexpr int OROW = MODE ? HD : FF;
    constexpr int NC   = KTOT / KC;

    const int e  = blockIdx.z;
    const int me = g_cnt[e];
    const int mt = blockIdx.y;
    if (mt * BM >= me) return;
    const int ntb = blockIdx.x * BN;

    extern __shared__ char smraw[];
    char* As = smraw;
    char* Bs = smraw + B_OFF;
    int*   stok  = (int*)(smraw + LIST_OFF);
    int*   sslot = stok + 128;
    float* sp0   = (float*)(sslot + 128);

    const int tid  = threadIdx.x;
    const int wid  = tid >> 5;
    const int lane = tid & 31;
    const int wm   = wid >> 2;       // 0..1
    const int wn   = wid & 3;        // 0..3
    const int lr   = lane >> 2;      // 0..7  (groupID)
    const int lc   = lane & 3;       // 0..3  (threadID_in_group)

    if (tid < 128) {
        int i = mt * BM + tid;
        int tok = 0, slot = -1;
        if (i < me) { tok = g_tok[e * TB + i]; slot = g_slot[e * TB + i]; }
        stok[tid] = tok; sslot[tid] = slot;
        if (MODE == 1) sp0[tid] = g_p0[tok];
    }
    __syncthreads();

    // ---- cp.async mappings (256 threads, 4 segs each per tile) ----
    const int mrow = tid >> 3;            // 0..31
    const int mseg = tid & 7;             // 0..7
    const __half* Asrc = MODE ? (const __half*)g_h : (const __half*)g_xh;
    const __half* aptr[4];
#pragma unroll
    for (int m = 0; m < 4; m++) {
        int row = mrow + 32 * m;
        int rid = MODE ? sslot[row] : stok[row];
        if (rid < 0) rid = 0;
        aptr[m] = Asrc + (size_t)rid * LDA + mseg * 8;
    }
    const uint32_t asmA = smem_u32(As) + (uint32_t)(mrow * ROWB + mseg * 16);

    const __half* bglob = W + (size_t)e * HD * FF + (size_t)(ntb + mrow) * KTOT + mseg * 8;
    const uint32_t bsmB = smem_u32(Bs) + (uint32_t)(mrow * ROWB + mseg * 16);

#define LOAD_CHUNK(STG, C)                                                    \
    {                                                                         \
        uint32_t as_ = asmA + (STG) * TSTG;                                   \
        _Pragma("unroll")                                                     \
        for (int m = 0; m < 4; m++)                                           \
            cp16(as_ + m * (32 * ROWB), aptr[m] + (C) * KC);                  \
        const __half* bg = bglob + (size_t)(C) * KC;                          \
        uint32_t bs_ = bsmB + (STG) * TSTG;                                   \
        _Pragma("unroll")                                                     \
        for (int m = 0; m < 4; m++)                                           \
            cp16(bs_ + m * (32 * ROWB), bg + (size_t)m * 32 * KTOT);          \
    }

    float acc[4][4][4];
#pragma unroll
    for (int i = 0; i < 4; i++)
#pragma unroll
        for (int j = 0; j < 4; j++)
#pragma unroll
            for (int r = 0; r < 4; r++) acc[i][j][r] = 0.f;

    LOAD_CHUNK(0, 0); CP_COMMIT();
    LOAD_CHUNK(1, 1); CP_COMMIT();

    // ---- ldmatrix per-thread base addresses ----
    const uint32_t aldm = smem_u32(As) +
        (uint32_t)((wm * 64 + (lane & 15)) * ROWB + ((lane >> 4) & 1) * 16);
    const uint32_t bldm = smem_u32(Bs) +
        (uint32_t)((wn * 32 + (lane & 7) + ((lane & 16) >> 1)) * ROWB + (lane & 8) * 2);

    for (int c = 0; c < NC; c++) {
        // wait for chunk c, one barrier, then issue loads for c+2
        CP_WAIT1();
        __syncthreads();
        const int pf = c + STAGES - 1;
        if (pf < NC) { LOAD_CHUNK(pf % STAGES, pf); }
        CP_COMMIT();

        const int st = c % STAGES;
        const uint32_t aS = aldm + st * TSTG;
        const uint32_t bS = bldm + st * TSTG;
#pragma unroll
        for (int k16 = 0; k16 < KC / 16; k16++) {
            const uint32_t ko = k16 * 32;    // 16 halves = 32 bytes
            uint32_t af[4][4], bf4[2][4];
#pragma unroll
            for (int i = 0; i < 4; i++)
                LDSM4(af[i], aS + i * (16 * ROWB) + ko);
#pragma unroll
            for (int jj = 0; jj < 2; jj++)
                LDSM4(bf4[jj], bS + jj * (16 * ROWB) + ko);
#pragma unroll
            for (int i = 0; i < 4; i++)
#pragma unroll
                for (int j = 0; j < 4; j++)
                    MMA_F16(acc[i][j], af[i], &bf4[j >> 1][(j & 1) * 2]);
        }
    }

    // ---- epilogue ----
    float bv[8];
#pragma unroll
    for (int j = 0; j < 4; j++) {
        float2 t = *(const float2*)(bias + e * OROW + ntb + wn * 32 + 8 * j + lc * 2);
        bv[2 * j] = t.x; bv[2 * j + 1] = t.y;
    }

#pragma unroll
    for (int i = 0; i < 4; i++) {
        const int mr0 = wm * 64 + 16 * i + lr;
        const int s0 = sslot[mr0];
        const int s1 = sslot[mr0 + 8];
#pragma unroll
        for (int j = 0; j < 4; j++) {
            const int n = ntb + wn * 32 + 8 * j + lc * 2;
            if (MODE == 0) {
                if (s0 >= 0) {
                    *(__half2*)(g_h + (size_t)s0 * OROW + n) = __floats2half2_rn(
                        fgelu(acc[i][j][0] + bv[2 * j]),
                        fgelu(acc[i][j][1] + bv[2 * j + 1]));
                }
                if (s1 >= 0) {
                    *(__half2*)(g_h + (size_t)s1 * OROW + n) = __floats2half2_rn(
                        fgelu(acc[i][j][2] + bv[2 * j]),
                        fgelu(acc[i][j][3] + bv[2 * j + 1]));
                }
            } else {
                if (s0 >= 0) {
                    float p = sp0[mr0];
                    float* op = outp + (size_t)stok[mr0] * HD + n;
                    atomicAdd(op,     p * (acc[i][j][0] + bv[2 * j]));
                    atomicAdd(op + 1, p * (acc[i][j][1] + bv[2 * j + 1]));
                }
                if (s1 >= 0) {
                    float p = sp0[mr0 + 8];
                    float* op = outp + (size_t)stok[mr0 + 8] * HD + n;
                    atomicAdd(op,     p * (acc[i][j][2] + bv[2 * j]));
                    atomicAdd(op + 1, p * (acc[i][j][3] + bv[2 * j + 1]));
                }
            }
        }
    }
}

// ---------------------------------------------------------------------------
extern "C" void kernel_launch(void* const* d_in, const int* in_sizes, int n_in,
                              void* d_out, int out_size) {
    const float* x  = (const float*)d_in[0];
    const float* Wr = (const float*)d_in[1];
    const float* br = (const float*)d_in[2];
    const float* W1 = (const float*)d_in[3];
    const float* b1 = (const float*)d_in[4];
    const float* W2 = (const float*)d_in[5];
    const float* b2 = (const float*)d_in[6];
    float* out = (float*)d_out;

    static bool init_done = false;
    static cudaStream_t s1, s2;
    static cudaEvent_t ev_root, ev1, ev2;
    if (!init_done) {
        cudaStreamCreateWithFlags(&s1, cudaStreamNonBlocking);
        cudaStreamCreateWithFlags(&s2, cudaStreamNonBlocking);
        cudaEventCreateWithFlags(&ev_root, cudaEventDisableTiming);
        cudaEventCreateWithFlags(&ev1, cudaEventDisableTiming);
        cudaEventCreateWithFlags(&ev2, cudaEventDisableTiming);
        cudaFuncSetAttribute(k_gemm<0>, cudaFuncAttributeMaxDynamicSharedMemorySize, SMEM_SZ);
        cudaFuncSetAttribute(k_gemm<1>, cudaFuncAttributeMaxDynamicSharedMemorySize, SMEM_SZ);
        init_done = true;
    }

    __half* gw1; cudaGetSymbolAddress((void**)&gw1, g_w1h);
    __half* gw2; cudaGetSymbolAddress((void**)&gw2, g_w2h);

    // fork: side streams carry cvt kernels + out-zero
    cudaEventRecord(ev_root, 0);
    cudaStreamWaitEvent(s1, ev_root, 0);
    cudaStreamWaitEvent(s2, ev_root, 0);

    dim3 t1(FF / 32, HD / 64, NE);   // W1 [HD][FF] -> [FF][HD]
    k_cvt_t<<<t1, 256, 0, s1>>>(W1, gw1, HD, FF);
    cudaEventRecord(ev1, s1);
    dim3 t2(HD / 32, FF / 64, NE);   // W2 [FF][HD] -> [HD][FF]
    k_cvt_t<<<t2, 256, 0, s2>>>(W2, gw2, FF, HD);
    k_zero<<<2048, 256, 0, s2>>>(out, out_size / 4);
    cudaEventRecord(ev2, s2);

    // stream 0: counters -> router (critical path to GEMM1)
    k_cnt0<<<1, 32>>>();
    k_router<<<TB / 8, 256>>>(x, Wr, br);

    // join: GEMM1 needs router + cvt(W1); GEMM2 additionally needs cvt(W2)+zero
    cudaStreamWaitEvent(0, ev1, 0);
    dim3 g1(FF / BN, TB / BM, NE);   // (32, 64, 8)
    k_gemm<0><<<g1, GT, SMEM_SZ>>>(gw1, b1, nullptr);
    cudaStreamWaitEvent(0, ev2, 0);
    dim3 g2(HD / BN, TB / BM, NE);   // (8, 64, 8)
    k_gemm<1><<<g2, GT, SMEM_SZ>>>(gw2, b2, out);
}